// round 17
// baseline (speedup 1.0000x reference)
#include <cuda_runtime.h>
#include <cuda_fp16.h>
#include <cstdint>
#include <math.h>

#define BB 4
#define TT 2048
#define DD 2048
#define HH 16
#define HDIM 128
#define MROWS (BB*TT)       /* 8192 */
#define K2 (2*DD)           /* 4096 row stride */
#define WPROJ_ROW0 (3*DD)   /* Wproj rows live at [6144,8192) of g_W2 */
#define PLANE_ELEMS ((size_t)BB*HH*TT*HDIM)   /* 16.8M */

// ---------------- scratch (device globals; uint4-backed => 16B align) ----------
__device__ uint4 g_A2_raw [(size_t)MROWS*K2/8];          // fp16, rows stride K2
__device__ uint4 g_W2_raw [(size_t)(4*DD)*K2/8];         // fp16, rows stride K2 (qkv + proj)
__device__ uint4 g_qh_raw [PLANE_ELEMS/8];               // fp16 planes (attention)
__device__ uint4 g_kh_raw [PLANE_ELEMS/8];
__device__ uint4 g_vh_raw [PLANE_ELEMS/8];
__device__ float g_sin[TT*64];
__device__ float g_cos[TT*64];
__device__ int   g_len[BB];

// device-code-only views (never use in host code / kernel args)
#define g_A2  ((__half*)g_A2_raw)
#define g_W2  ((__half*)g_W2_raw)
#define g_qh  ((__half*)g_qh_raw)
#define g_kh  ((__half*)g_kh_raw)
#define g_vh  ((__half*)g_vh_raw)

// ============================ helpers ============================
__device__ __forceinline__ uint32_t smem_u32(const void* p) {
    uint32_t a;
    asm("{ .reg .u64 t; cvta.to.shared.u64 t, %1; cvt.u32.u64 %0, t; }" : "=r"(a) : "l"(p));
    return a;
}
__device__ __forceinline__ void cp16(uint32_t s, const void* g) {
    asm volatile("cp.async.cg.shared.global [%0], [%1], 16;" :: "r"(s), "l"(g));
}
__device__ __forceinline__ void ldmx4(uint32_t* r, uint32_t addr) {
    asm volatile("ldmatrix.sync.aligned.m8n8.x4.shared.b16 {%0,%1,%2,%3}, [%4];"
        : "=r"(r[0]), "=r"(r[1]), "=r"(r[2]), "=r"(r[3]) : "r"(addr));
}
__device__ __forceinline__ void ldmx4t(uint32_t* r, uint32_t addr) {
    asm volatile("ldmatrix.sync.aligned.m8n8.x4.trans.shared.b16 {%0,%1,%2,%3}, [%4];"
        : "=r"(r[0]), "=r"(r[1]), "=r"(r[2]), "=r"(r[3]) : "r"(addr));
}
__device__ __forceinline__ void mma16816h(float* d, const uint32_t* a, uint32_t b0, uint32_t b1) {
    asm volatile("mma.sync.aligned.m16n8k16.row.col.f32.f16.f16.f32 "
        "{%0,%1,%2,%3}, {%4,%5,%6,%7}, {%8,%9}, {%0,%1,%2,%3};"
        : "+f"(d[0]), "+f"(d[1]), "+f"(d[2]), "+f"(d[3])
        : "r"(a[0]), "r"(a[1]), "r"(a[2]), "r"(a[3]), "r"(b0), "r"(b1));
}
__device__ __forceinline__ uint32_t pack_h2(float lo, float hi) {
    union { __half2 h; uint32_t u; } t;
    t.h = __floats2half2_rn(lo, hi);
    return t.u;
}
#define SWZ8(c, r)  ((c) ^ ((r) & 7))

// ---------------- fused preprocessing: convs + sctab + lengths ----------------
// blocks [0,8192): x rows -> g_A2 ; [8192,14336): Wqkv rows -> g_W2 ;
// [14336,16384): Wproj rows -> g_W2 + WPROJ_ROW0 ; [16384,16896): sctab ;
// [16896,16900): lengths
#define PREP_BLOCKS 16900

__global__ __launch_bounds__(256) void prep_kernel(
    const float* __restrict__ x, const float* __restrict__ Wqkv,
    const float* __restrict__ Wproj, const int* __restrict__ mask)
{
    const int bid = blockIdx.x, tid = threadIdx.x;
    if (bid < 16384) {
        // fp32 row -> fp16 row (8 elems/thread, ld.128 x2 -> st.128)
        const float* src;
        __half* dst;
        if (bid < 8192)       { src = x     + (size_t)bid * DD;          dst = g_A2 + (size_t)bid * K2; }
        else if (bid < 14336) { int r = bid - 8192;  src = Wqkv  + (size_t)r * DD; dst = g_W2 + (size_t)r * K2; }
        else                  { int r = bid - 14336; src = Wproj + (size_t)r * DD; dst = g_W2 + (size_t)(WPROJ_ROW0 + r) * K2; }
        float4 v0 = *(const float4*)(src + tid * 8);
        float4 v1 = *(const float4*)(src + tid * 8 + 4);
        union { __half b[8]; uint4 u; } h;
        h.b[0] = __float2half_rn(v0.x); h.b[1] = __float2half_rn(v0.y);
        h.b[2] = __float2half_rn(v0.z); h.b[3] = __float2half_rn(v0.w);
        h.b[4] = __float2half_rn(v1.x); h.b[5] = __float2half_rn(v1.y);
        h.b[6] = __float2half_rn(v1.z); h.b[7] = __float2half_rn(v1.w);
        *(uint4*)(dst + tid * 8) = h.u;
    } else if (bid < 16896) {
        int idx = (bid - 16384) * 256 + tid;       // TT*64
        int d = idx & 63, t = idx >> 6;
        float inv = (float)exp(-(double)(2 * d) / 128.0 * 9.210340371976184);
        float ang = (float)t * inv;
        float s, c;
        sincosf(ang, &s, &c);
        g_sin[idx] = s;
        g_cos[idx] = c;
    } else {
        __shared__ int sd[256];
        int b = bid - 16896;
        int s = 0;
        for (int i = tid; i < TT; i += 256) s += mask[b * TT + i];
        sd[tid] = s;
        __syncthreads();
        for (int st = 128; st > 0; st >>= 1) {
            if (tid < st) sd[tid] += sd[tid + st];
            __syncthreads();
        }
        if (tid == 0) g_len[b] = sd[0];
    }
}

// ---------------- HMMA fp16 GEMM (single plane, K=2048), persistent ----------
// MODE 0: QKV (3072 tiles). q/k epilogue fuses RoPE; v writes fp16 plane;
//          k/v tiles beyond valid length skipped.
// MODE 1: proj (1024 tiles), fp32 out, weights at g_W2+WPROJ_ROW0.
#define GSTAGE 32768
#define SMEM_GEMM_TOTAL (3*GSTAGE)      /* 98304 B */
#define GITERS (DD/64)                  /* 32 */

template <int MODE>
__global__ __launch_bounds__(128, 2) void gemm_mma(float* __restrict__ Cout) {
    extern __shared__ __align__(16) char smraw[];
    const uint32_t sb = smem_u32(smraw);
    const int tid = threadIdx.x;
    const int warp = tid >> 5, lane = tid & 31;
    const int wm = warp >> 1, wn = warp & 1;

    const int lrow = (lane & 7) + 8 * ((lane >> 3) & 1);
    const int lch  = lane >> 4;
    uint32_t aro[4], bro[4];
#pragma unroll
    for (int mi = 0; mi < 4; mi++) {
        int row = wm * 64 + mi * 16 + lrow;
        aro[mi] = row * 128 + ((row & 7) << 4);
    }
#pragma unroll
    for (int n16 = 0; n16 < 4; n16++) {
        int nr = wn * 64 + n16 * 16 + lrow;
        bro[n16] = 16384 + nr * 128 + ((nr & 7) << 4);
    }
    const int r0 = tid >> 3;                       // 0..15
    const int c0 = tid & 7;
    const uint32_t soA0 = r0 * 128 + SWZ8(c0, r0) * 16;
    const uint32_t soB0 = 16384 + soA0;

    const int NT = (MODE == 0) ? 48 * 64 : 16 * 64;

    for (int tile = blockIdx.x; tile < NT; tile += gridDim.x) {
        int bn, bm;
        if (MODE == 0) { bn = (tile % 48) * 128; bm = (tile / 48) * 128; }
        else           { bn = (tile % 16) * 128; bm = (tile / 16) * 128; }

        if (MODE == 0) {
            const int which = bn >> 11;
            if (which >= 1 && (bm & (TT - 1)) >= g_len[bm >> 11]) continue;
        }
        __syncthreads();                           // smem stage reuse guard

        float acc[32][4];
#pragma unroll
        for (int i = 0; i < 32; i++)
#pragma unroll
            for (int j = 0; j < 4; j++) acc[i][j] = 0.f;

        const __half* pA = g_A2 + (size_t)(bm + r0) * K2 + c0 * 8;
        const __half* pB = g_W2 + (size_t)((MODE ? WPROJ_ROW0 : 0) + bn + r0) * K2 + c0 * 8;

        auto load_stage = [&](uint32_t sbase) {
#pragma unroll
            for (int l = 0; l < 8; l++) {
                cp16(sbase + soA0 + l * 2048, pA + (size_t)l * 16 * K2);
                cp16(sbase + soB0 + l * 2048, pB + (size_t)l * 16 * K2);
            }
            asm volatile("cp.async.commit_group;" ::: "memory");
            pA += 64; pB += 64;
        };

        load_stage(sb);
        load_stage(sb + GSTAGE);

        for (int i = 0; i < GITERS; i += 3) {
#pragma unroll
            for (int u = 0; u < 3; u++) {
                const int idx = i + u;
                if (idx >= GITERS) break;
                if (idx >= GITERS - 2) asm volatile("cp.async.wait_group 0;" ::: "memory");
                else                   asm volatile("cp.async.wait_group 1;" ::: "memory");
                __syncthreads();
                if (idx + 2 < GITERS) load_stage(sb + ((u + 2) % 3) * GSTAGE);

                const uint32_t sa = sb + u * GSTAGE;
#pragma unroll
                for (int ks = 0; ks < 4; ks++) {
                    const uint32_t chx = (uint32_t)(ks * 2 + lch) << 4;
                    uint32_t a[4][4], b[4][4];
#pragma unroll
                    for (int mi = 0; mi < 4; mi++)
                        ldmx4(a[mi], sa + (aro[mi] ^ chx));
#pragma unroll
                    for (int n16 = 0; n16 < 4; n16++)
                        ldmx4(b[n16], sa + (bro[n16] ^ chx));
#pragma unroll
                    for (int mi = 0; mi < 4; mi++)
#pragma unroll
                        for (int n16 = 0; n16 < 4; n16++) {
                            mma16816h(acc[mi * 8 + n16 * 2],     a[mi], b[n16][0], b[n16][2]);
                            mma16816h(acc[mi * 8 + n16 * 2 + 1], a[mi], b[n16][1], b[n16][3]);
                        }
                }
            }
        }

        // ---- epilogue ----
        if (MODE == 0) {
            const int which = bn >> 11;            // 0=q 1=k 2=v
            const int h = (bn >> 7) & 15;
            if (which == 2) {
#pragma unroll
                for (int mi = 0; mi < 4; mi++)
#pragma unroll
                    for (int nn = 0; nn < 8; nn++) {
                        int d = wn * 64 + (nn >> 1) * 16 + (nn & 1) * 8 + (lane & 3) * 2;
#pragma unroll
                        for (int half = 0; half < 2; half++) {
                            int m = bm + wm * 64 + mi * 16 + (lane >> 2) + half * 8;
                            int b_ = m >> 11, t_ = m & (TT - 1);
                            size_t off = (((size_t)b_ * HH + h) * TT + t_) * HDIM + d;
                            *(uint32_t*)&g_vh[off] = pack_h2(acc[mi * 8 + nn][2 * half],
                                                             acc[mi * 8 + nn][2 * half + 1]);
                        }
                    }
            } else {
                // fused RoPE: stage fp32 tile in smem (pitch 130), rotate, write fp16
                __syncthreads();                   // mainloop smem reads done
                float* smf = (float*)smraw;
#pragma unroll
                for (int mi = 0; mi < 4; mi++)
#pragma unroll
                    for (int nn = 0; nn < 8; nn++) {
                        int c = wn * 64 + (nn >> 1) * 16 + (nn & 1) * 8 + (lane & 3) * 2;
#pragma unroll
                        for (int half = 0; half < 2; half++) {
                            int r = wm * 64 + mi * 16 + (lane >> 2) + half * 8;
                            smf[r * 130 + c]     = acc[mi * 8 + nn][2 * half];
                            smf[r * 130 + c + 1] = acc[mi * 8 + nn][2 * half + 1];
                        }
                    }
                __syncthreads();
                __half* dst = (which == 0) ? g_qh : g_kh;
                const int d = tid & 63;
                const int rh = tid >> 6;           // 0..1
                const int b_ = bm >> 11;
#pragma unroll 4
                for (int rr = 0; rr < 64; rr++) {
                    int r = rh * 64 + rr;
                    int t_ = (bm + r) & (TT - 1);
                    int ti = (t_ << 6) + d;
                    float s = g_sin[ti], c = g_cos[ti];
                    float v1 = smf[r * 130 + d];
                    float v2 = smf[r * 130 + d + 64];
                    size_t off = (((size_t)b_ * HH + h) * TT + t_) * HDIM;
                    dst[off + d]      = __float2half_rn(v1 * c - v2 * s);
                    dst[off + d + 64] = __float2half_rn(v2 * c + v1 * s);
                }
            }
        } else {
#pragma unroll
            for (int mi = 0; mi < 4; mi++)
#pragma unroll
                for (int nn = 0; nn < 8; nn++) {
                    int col = bn + wn * 64 + (nn >> 1) * 16 + (nn & 1) * 8 + (lane & 3) * 2;
#pragma unroll
                    for (int half = 0; half < 2; half++) {
                        int m = bm + wm * 64 + mi * 16 + (lane >> 2) + half * 8;
                        float2 v2 = make_float2(acc[mi * 8 + nn][2 * half],
                                                acc[mi * 8 + nn][2 * half + 1]);
                        *(float2*)&Cout[(size_t)m * DD + col] = v2;
                    }
                }
        }
    }
}

// ---------------- fp16 flash attention: BQ=128, BKV=64, 8 warps ----------------
// S = Qh*Kh (1 term); O = Ph*Vh (1 term, fp16 P)
#define AQ_OFF   0
#define AKV_OFF  32768
#define AKV_STG  32768
#define SMEM_ATTN_TOTAL (32768 + 2*32768)   /* 98304 */

__global__ __launch_bounds__(256) void attn_mma_kernel() {
    extern __shared__ __align__(16) char smraw[];
    const uint32_t sb = smem_u32(smraw);
    const int tid = threadIdx.x;
    const int warp = tid >> 5, lane = tid & 31;
    const int qt = 15 - blockIdx.x;                 // descending work order
    const int h = blockIdx.y, b = blockIdx.z;
    const int L = g_len[b];
    const size_t bhT = ((size_t)b * HH + h) * TT;

    const int lrow = (lane & 7) + 8 * ((lane >> 3) & 1);
    const int lch  = lane >> 4;

    // ---- load Q tile (qh only), own commit group ----
    {
#pragma unroll
        for (int l = 0; l < 8; l++) {
            int idx = tid + l * 256;                // 2048 chunks
            int row = idx >> 4, c = idx & 15;
            cp16(sb + AQ_OFF + row * 256 + SWZ8(c, row) * 16,
                 g_qh + (bhT + (size_t)qt * 128 + row) * HDIM + c * 8);
        }
        asm volatile("cp.async.commit_group;" ::: "memory");
    }

    const int nt = (min(qt * 128 + 128, L) + 63) / 64;

    auto load_kv = [&](int kt, int stg) {
        const __half* pp[2];
        pp[0] = g_kh; pp[1] = g_vh;
        uint32_t base = sb + AKV_OFF + stg * AKV_STG;
#pragma unroll
        for (int l = 0; l < 8; l++) {
            int idx = tid + l * 256;                // 2048 chunks
            int pl = idx >> 10, rem = idx & 1023;
            int row = rem >> 4, c = rem & 15;
            cp16(base + pl * 16384 + row * 256 + SWZ8(c, row) * 16,
                 pp[pl] + (bhT + (size_t)kt * 64 + row) * HDIM + c * 8);
        }
        asm volatile("cp.async.commit_group;" ::: "memory");
    };
    load_kv(0, 0);

    // ---- hoist Q fragments (wait only for the Q group) ----
    uint32_t qhf[8][4];
    {
        asm volatile("cp.async.wait_group 1;" ::: "memory");
        __syncthreads();
        const uint32_t qh = sb + AQ_OFF;
        const int arow = warp * 16 + lrow;
#pragma unroll
        for (int k16 = 0; k16 < 8; k16++) {
            const int ch = k16 * 2 + lch;
            ldmx4(qhf[k16], qh + arow * 256 + SWZ8(ch, arow) * 16);
        }
    }

    float oacc[16][4];
#pragma unroll
    for (int i = 0; i < 16; i++)
#pragma unroll
        for (int j = 0; j < 4; j++) oacc[i][j] = 0.f;
    float m0 = -1e30f, m1 = -1e30f, l0 = 0.f, l1 = 0.f;

    const int wr = qt * 128 + warp * 16;
    const float scl = 0.08838834764831843f;

    for (int kt = 0; kt < nt; kt++) {
        asm volatile("cp.async.wait_group 0;" ::: "memory");
        __syncthreads();
        if (kt + 1 < nt) load_kv(kt + 1, (kt + 1) & 1);

        const uint32_t kh = sb + AKV_OFF + (kt & 1) * AKV_STG;
        const uint32_t vh = kh + 16384;

        // ---- S = Qh*Kh ----
        float sacc[8][4];
#pragma unroll
        for (int i = 0; i < 8; i++)
#pragma unroll
            for (int j = 0; j < 4; j++) sacc[i][j] = 0.f;

#pragma unroll
        for (int k16 = 0; k16 < 8; k16++) {
            const int ch = k16 * 2 + lch;
#pragma unroll
            for (int n16 = 0; n16 < 4; n16++) {
                const int nr = n16 * 16 + lrow;
                uint32_t bh[4];
                ldmx4(bh, kh + nr * 256 + SWZ8(ch, nr) * 16);
                mma16816h(sacc[2*n16],   qhf[k16], bh[0], bh[2]);
                mma16816h(sacc[2*n16+1], qhf[k16], bh[1], bh[3]);
            }
        }

        // ---- mask + online softmax ----
        const bool needmask = ((kt + 1) * 64 > qt * 128) || ((kt + 1) * 64 > L);
        const int r0g = wr + (lane >> 2);
#pragma unroll
        for (int f = 0; f < 8; f++)
#pragma unroll
            for (int c = 0; c < 4; c++) {
                float x = sacc[f][c] * scl;
                if (needmask) {
                    int col = kt * 64 + f * 8 + ((lane & 3) << 1) + (c & 1);
                    int rg = r0g + ((c >> 1) << 3);
                    if (col > rg || col >= L) x = -1e30f;
                }
                sacc[f][c] = x;
            }
        float mx0 = -1e30f, mx1 = -1e30f;
#pragma unroll
        for (int f = 0; f < 8; f++) {
            mx0 = fmaxf(mx0, fmaxf(sacc[f][0], sacc[f][1]));
            mx1 = fmaxf(mx1, fmaxf(sacc[f][2], sacc[f][3]));
        }
        mx0 = fmaxf(mx0, __shfl_xor_sync(0xffffffffu, mx0, 1));
        mx0 = fmaxf(mx0, __shfl_xor_sync(0xffffffffu, mx0, 2));
        mx1 = fmaxf(mx1, __shfl_xor_sync(0xffffffffu, mx1, 1));
        mx1 = fmaxf(mx1, __shfl_xor_sync(0xffffffffu, mx1, 2));
        float mn0 = fmaxf(m0, mx0), mn1 = fmaxf(m1, mx1);
        float corr0 = __expf(m0 - mn0), corr1 = __expf(m1 - mn1);
        float sum0 = 0.f, sum1 = 0.f;
#pragma unroll
        for (int f = 0; f < 8; f++) {
            float p;
            p = __expf(sacc[f][0] - mn0); sacc[f][0] = p; sum0 += p;
            p = __expf(sacc[f][1] - mn0); sacc[f][1] = p; sum0 += p;
            p = __expf(sacc[f][2] - mn1); sacc[f][2] = p; sum1 += p;
            p = __expf(sacc[f][3] - mn1); sacc[f][3] = p; sum1 += p;
        }
        sum0 += __shfl_xor_sync(0xffffffffu, sum0, 1);
        sum0 += __shfl_xor_sync(0xffffffffu, sum0, 2);
        sum1 += __shfl_xor_sync(0xffffffffu, sum1, 1);
        sum1 += __shfl_xor_sync(0xffffffffu, sum1, 2);
        l0 = l0 * corr0 + sum0; m0 = mn0;
        l1 = l1 * corr1 + sum1; m1 = mn1;
#pragma unroll
        for (int nf = 0; nf < 16; nf++) {
            oacc[nf][0] *= corr0; oacc[nf][1] *= corr0;
            oacc[nf][2] *= corr1; oacc[nf][3] *= corr1;
        }

        // ---- O += Ph*Vh (single fp16 P plane) ----
#pragma unroll
        for (int j16 = 0; j16 < 4; j16++) {
            const int f0 = 2 * j16, f1 = 2 * j16 + 1;
            uint32_t aPh[4];
            aPh[0] = pack_h2(sacc[f0][0], sacc[f0][1]);
            aPh[1] = pack_h2(sacc[f0][2], sacc[f0][3]);
            aPh[2] = pack_h2(sacc[f1][0], sacc[f1][1]);
            aPh[3] = pack_h2(sacc[f1][2], sacc[f1][3]);
#pragma unroll
            for (int d16 = 0; d16 < 8; d16++) {
                const int ch = d16 * 2 + lch;
                const int vr = j16 * 16 + lrow;
                uint32_t bvh[4];
                ldmx4t(bvh, vh + vr * 256 + SWZ8(ch, vr) * 16);
                mma16816h(oacc[2*d16],   aPh, bvh[0], bvh[1]);
                mma16816h(oacc[2*d16+1], aPh, bvh[2], bvh[3]);
            }
        }
        __syncthreads();
    }

    // ---- epilogue: write hi plane into g_A2 ----
    const float il0 = 1.f / l0, il1 = 1.f / l1;
    const int trow = qt * 128 + warp * 16 + (lane >> 2);
#pragma unroll
    for (int nf = 0; nf < 16; nf++) {
        int col = h * 128 + nf * 8 + (lane & 3) * 2;
#pragma unroll
        for (int half = 0; half < 2; half++) {
            float v0 = oacc[nf][2 * half]     * (half ? il1 : il0);
            float v1 = oacc[nf][2 * half + 1] * (half ? il1 : il0);
            __half* row = g_A2 + ((size_t)b * TT + trow + half * 8) * K2;
            *(uint32_t*)&row[col] = pack_h2(v0, v1);
        }
    }
}

// ---------------- launcher ----------------
extern "C" void kernel_launch(void* const* d_in, const int* in_sizes, int n_in,
                              void* d_out, int out_size) {
    const float* x     = (const float*)d_in[0];
    const float* Wqkv  = (const float*)d_in[1];
    const float* Wproj = (const float*)d_in[2];
    const int*   mask  = (const int*)d_in[3];
    float* out = (float*)d_out;

    int nsm = 148;
    cudaDeviceGetAttribute(&nsm, cudaDevAttrMultiProcessorCount, 0);

    cudaFuncSetAttribute(gemm_mma<0>, cudaFuncAttributeMaxDynamicSharedMemorySize, SMEM_GEMM_TOTAL);
    cudaFuncSetAttribute(gemm_mma<1>, cudaFuncAttributeMaxDynamicSharedMemorySize, SMEM_GEMM_TOTAL);
    cudaFuncSetAttribute(attn_mma_kernel, cudaFuncAttributeMaxDynamicSharedMemorySize, SMEM_ATTN_TOTAL);

    prep_kernel<<<PREP_BLOCKS, 256>>>(x, Wqkv, Wproj, mask);
    gemm_mma<0><<<2 * nsm, 128, SMEM_GEMM_TOTAL>>>(nullptr);
    attn_mma_kernel<<<dim3(16, HH, BB), 256, SMEM_ATTN_TOTAL>>>();
    gemm_mma<1><<<2 * nsm, 128, SMEM_GEMM_TOTAL>>>(out);
}